// round 11
// baseline (speedup 1.0000x reference)
#include <cuda_runtime.h>

#define NN     1024
#define NBLK   288
#define RPB    18
#define NTHR   512
#define NWARP  16
#define CHUNK  57
#define ROWCAP 32
#define SEGCAP 8
#define W_WIN  0.75f
#define WB     0.716f

#define K_EPSLOGMU  (-6.9314616e-3f)
#define K_L2E_EPS   (1442.6950409f)
#define K_CUT       (-0.032f)

__device__ float  g_C[16u * 1024u * 1024u];
__device__ float  g_u[16384], g_v[16384];
__device__ float2 g_part[NBLK * 1024];
__device__ float  g_errpart[2][NBLK];
__device__ float  g_costpart[NBLK];
__device__ int2   g_rlist[16384u * ROWCAP];
__device__ int    g_rcnt[16384];
__device__ int2   g_clist[16384u * 18u * SEGCAP];
__device__ int    g_ccnt[16384 * 18];
__device__ unsigned g_du[2][16], g_dv[2][16];
__device__ unsigned g_count, g_release;

__device__ __forceinline__ float ex2f(float x) {
    float r;
    asm("ex2.approx.ftz.f32 %0, %1;" : "=f"(r) : "f"(x));
    return r;
}

// ---------------------------------------------------------------------------
__global__ void compute_C_kernel(const float* __restrict__ X,
                                 const float* __restrict__ Y) {
    __shared__ float xs[32][33];
    __shared__ float ys[32][33];
    int b  = blockIdx.z;
    int i0 = blockIdx.y * 32;
    int j0 = blockIdx.x * 32;
    int tid = threadIdx.x;

    if (blockIdx.y == 0 && blockIdx.z == 0) {
        for (int i = blockIdx.x * 256 + tid; i < 16384; i += 8192) {
            g_u[i] = 0.f; g_v[i] = 0.f;
        }
        if (blockIdx.x == 0 && tid < 16) {
            g_du[0][tid] = g_du[1][tid] = 0u;
            g_dv[0][tid] = g_dv[1][tid] = 0u;
            if (tid == 0) { g_count = 0u; g_release = 0u; }
        }
    }

    const float* xp = X + ((size_t)(b * NN + i0)) * 32;
    const float* yp = Y + ((size_t)(b * NN + j0)) * 32;
    for (int idx = tid; idx < 1024; idx += 256) {
        xs[idx >> 5][idx & 31] = xp[idx];
        ys[idx >> 5][idx & 31] = yp[idx];
    }
    __syncthreads();

    int tx = tid & 31;
    int ty = tid >> 5;
    float a0 = 0.f, a1 = 0.f, a2 = 0.f, a3 = 0.f;
#pragma unroll
    for (int d = 0; d < 32; d++) {
        float yv = ys[tx][d];
        float d0 = xs[ty][d]      - yv; a0 += d0 * d0;
        float d1 = xs[ty +  8][d] - yv; a1 += d1 * d1;
        float d2 = xs[ty + 16][d] - yv; a2 += d2 * d2;
        float d3 = xs[ty + 24][d] - yv; a3 += d3 * d3;
    }
    size_t base = ((size_t)b << 20);
    g_C[base + ((size_t)(i0 + ty)      << 10) + j0 + tx] = a0;
    g_C[base + ((size_t)(i0 + ty +  8) << 10) + j0 + tx] = a1;
    g_C[base + ((size_t)(i0 + ty + 16) << 10) + j0 + tx] = a2;
    g_C[base + ((size_t)(i0 + ty + 24) << 10) + j0 + tx] = a3;
}

// ---------------------------------------------------------------------------
__device__ __forceinline__ void grid_barrier(unsigned target) {
    __syncthreads();
    if (threadIdx.x == 0) {
        __threadfence();
        if (atomicAdd(&g_count, 1u) == NBLK - 1u) {
            g_count = 0u;
            __threadfence();
            atomicAdd(&g_release, 1u);
        } else {
            while (*((volatile unsigned*)&g_release) < target) { __nanosleep(32); }
        }
        __threadfence();
    }
    __syncthreads();
}

#define VUPS(mm, ss, xx) do {                                                 \
    float x_  = (xx);                                                         \
    float hi_ = fmaxf(mm, x_);                                                \
    float d_  = fminf(mm, x_) - hi_;                                          \
    float e_  = (d_ >= K_CUT) ? ex2f(d_ * K_L2E_EPS) : 0.f;                   \
    ss = (x_ > (mm)) ? fmaf(ss, e_, 1.f) : (ss + e_);                         \
    mm = hi_;                                                                 \
} while (0)

#define PCOMB(M, S, pm, ps) do {                                              \
    if ((pm) > (M)) {                                                         \
        float d_ = (M) - (pm);                                                \
        (S) = (S) * ((d_ >= K_CUT) ? ex2f(d_ * K_L2E_EPS) : 0.f) + (ps);      \
        (M) = (pm);                                                           \
    } else {                                                                  \
        float d_ = (pm) - (M);                                                \
        if (d_ >= K_CUT) (S) += (ps) * ex2f(d_ * K_L2E_EPS);                  \
    }                                                                         \
} while (0)

// ---------------------------------------------------------------------------
__global__ __launch_bounds__(NTHR, 2) void sinkhorn_kernel(float* __restrict__ out) {
    __shared__ __align__(16) float s_v[1024];
    __shared__ float s_u[64];
    __shared__ float s_red[NWARP], s_redm[NWARP];
    __shared__ float s_bcast;

    int tid  = threadIdx.x;
    int lane = tid & 31;
    int warp = tid >> 5;
    int b    = blockIdx.x / RPB;
    int r    = blockIdx.x % RPB;
    int row0 = r * CHUNK;
    int cnt  = (r == RPB - 1) ? (NN - row0) : CHUNK;
    const float4* sv4 = (const float4*)s_v;
    const float2* cr2 = (const float2*)(g_C + ((size_t)b << 20) + ((size_t)row0 << 10));
    unsigned lmlt = (1u << lane) - 1u;
    unsigned bar = 0;

    float acc_du = 0.f, acc_dv = 0.f, dv_last = 1e30f;
    bool rowvalid = false, colvalid = false;

    if (tid < 64) s_u[tid] = 0.f;

    for (int iter = 0; iter < 100; iter++) {
        int p = iter & 1;
        for (int j = tid; j < 1024; j += NTHR)
            s_v[j] = __ldcg(&g_v[(b << 10) + j]);
        __syncthreads();

        bool u_full    = !(rowvalid && 2.f * acc_dv <= WB);
        bool build_row = u_full && (2.f * dv_last <= WB);
        float ei = 0.f, dumax = 0.f;

        if (u_full) {
            // ---- FULL u-pass (warp/row) + optional list build ----
            for (int idx = warp; idx < cnt; idx += NWARP) {
                int grow = (b << 10) + row0 + idx;
                const float4* cr = (const float4*)(g_C + ((size_t)grow << 10));
                float ma = -3.0e38f, mb = -3.0e38f;
#pragma unroll
                for (int k = 0; k < 8; k += 2) {
                    float4 c0 = cr[k * 32 + lane], c1 = cr[(k + 1) * 32 + lane];
                    float4 v0 = sv4[k * 32 + lane], v1 = sv4[(k + 1) * 32 + lane];
                    ma = fmaxf(ma, fmaxf(fmaxf(v0.x - c0.x, v0.y - c0.y),
                                         fmaxf(v0.z - c0.z, v0.w - c0.w)));
                    mb = fmaxf(mb, fmaxf(fmaxf(v1.x - c1.x, v1.y - c1.y),
                                         fmaxf(v1.z - c1.z, v1.w - c1.w)));
                }
                float m = fmaxf(ma, mb);
#pragma unroll
                for (int off = 16; off; off >>= 1)
                    m = fmaxf(m, __shfl_xor_sync(0xffffffffu, m, off));
                float mw = build_row ? (m - W_WIN) : (m + K_CUT);
                float s = 0.f;
                int bc = 0;
#pragma unroll
                for (int k = 0; k < 8; k++) {
                    float4 c = cr[k * 32 + lane];
                    float4 v = sv4[k * 32 + lane];
                    float x0 = v.x - c.x, x1 = v.y - c.y;
                    float x2 = v.z - c.z, x3 = v.w - c.w;
                    float mx = fmaxf(fmaxf(x0, x1), fmaxf(x2, x3));
                    if (__any_sync(0xffffffffu, mx >= mw)) {
                        float t;
                        t = x0 - m; if (t >= K_CUT) s += ex2f(t * K_L2E_EPS);
                        t = x1 - m; if (t >= K_CUT) s += ex2f(t * K_L2E_EPS);
                        t = x2 - m; if (t >= K_CUT) s += ex2f(t * K_L2E_EPS);
                        t = x3 - m; if (t >= K_CUT) s += ex2f(t * K_L2E_EPS);
                        if (build_row) {
                            int jb = (k * 32 + lane) * 4;
#define APP_R(xx, cc, ee) {                                                   \
    bool cd = ((xx) >= mw);                                                   \
    unsigned mk2 = __ballot_sync(0xffffffffu, cd);                            \
    if (cd) { int pos = bc + __popc(mk2 & lmlt);                              \
        if (pos < ROWCAP) g_rlist[(size_t)grow * ROWCAP + pos] =              \
            make_int2(jb + (ee), __float_as_int(cc)); }                       \
    bc += __popc(mk2); }
                            APP_R(x0, c.x, 0) APP_R(x1, c.y, 1)
                            APP_R(x2, c.z, 2) APP_R(x3, c.w, 3)
#undef APP_R
                        }
                    }
                }
#pragma unroll
                for (int off = 16; off; off >>= 1)
                    s += __shfl_xor_sync(0xffffffffu, s, off);
                if (lane == 0) {
                    float nu = K_EPSLOGMU - m - 1e-3f * __logf(s);
                    float d = fabsf(nu - s_u[idx]);
                    ei += d; dumax = fmaxf(dumax, d);
                    s_u[idx] = nu; g_u[grow] = nu;
                    if (build_row) g_rcnt[grow] = bc;
                }
            }
        } else {
            // ---- CHEAP u-pass (candidates, warp/row) ----
            for (int idx = warp; idx < cnt; idx += NWARP) {
                int grow = (b << 10) + row0 + idx;
                int rc = g_rcnt[grow];
                float m, s;
                if (rc <= ROWCAP) {
                    float sc = -3.0e38f;
                    if (lane < rc) {
                        int2 en = g_rlist[(size_t)grow * ROWCAP + lane];
                        sc = s_v[en.x] - __int_as_float(en.y);
                    }
                    m = sc;
#pragma unroll
                    for (int off = 16; off; off >>= 1)
                        m = fmaxf(m, __shfl_xor_sync(0xffffffffu, m, off));
                    float t = sc - m;
                    s = (t >= K_CUT) ? ex2f(t * K_L2E_EPS) : 0.f;
#pragma unroll
                    for (int off = 16; off; off >>= 1)
                        s += __shfl_xor_sync(0xffffffffu, s, off);
                } else {
                    const float4* cr = (const float4*)(g_C + ((size_t)grow << 10));
                    float ma = -3.0e38f;
#pragma unroll
                    for (int k = 0; k < 8; k++) {
                        float4 c = cr[k * 32 + lane];
                        float4 v = sv4[k * 32 + lane];
                        ma = fmaxf(ma, fmaxf(fmaxf(v.x - c.x, v.y - c.y),
                                             fmaxf(v.z - c.z, v.w - c.w)));
                    }
                    m = ma;
#pragma unroll
                    for (int off = 16; off; off >>= 1)
                        m = fmaxf(m, __shfl_xor_sync(0xffffffffu, m, off));
                    float mk = m + K_CUT;
                    s = 0.f;
#pragma unroll
                    for (int k = 0; k < 8; k++) {
                        float4 c = cr[k * 32 + lane];
                        float4 v = sv4[k * 32 + lane];
                        float x0 = v.x - c.x, x1 = v.y - c.y;
                        float x2 = v.z - c.z, x3 = v.w - c.w;
                        float mx = fmaxf(fmaxf(x0, x1), fmaxf(x2, x3));
                        if (__any_sync(0xffffffffu, mx >= mk)) {
                            float t;
                            t = x0 - m; if (t >= K_CUT) s += ex2f(t * K_L2E_EPS);
                            t = x1 - m; if (t >= K_CUT) s += ex2f(t * K_L2E_EPS);
                            t = x2 - m; if (t >= K_CUT) s += ex2f(t * K_L2E_EPS);
                            t = x3 - m; if (t >= K_CUT) s += ex2f(t * K_L2E_EPS);
                        }
                    }
#pragma unroll
                    for (int off = 16; off; off >>= 1)
                        s += __shfl_xor_sync(0xffffffffu, s, off);
                }
                if (lane == 0) {
                    float nu = K_EPSLOGMU - m - 1e-3f * __logf(s);
                    float d = fabsf(nu - s_u[idx]);
                    ei += d; dumax = fmaxf(dumax, d);
                    s_u[idx] = nu; g_u[grow] = nu;
                }
            }
        }

        if (lane == 0) { s_red[warp] = ei; s_redm[warp] = dumax; }
        __syncthreads();
        if (warp == 0) {
            float t2 = (lane < NWARP) ? s_red[lane] : 0.f;
            float t3 = (lane < NWARP) ? s_redm[lane] : 0.f;
#pragma unroll
            for (int off = 16; off; off >>= 1) {
                t2 += __shfl_xor_sync(0xffffffffu, t2, off);
                t3 = fmaxf(t3, __shfl_xor_sync(0xffffffffu, t3, off));
            }
            if (lane == 0) {
                g_errpart[p][blockIdx.x] = t2;
                atomicMax(&g_du[p][b], __float_as_uint(t3));
            }
        }

        grid_barrier(++bar);                     // A: u, err, du final

        if (warp == 0) {
            float t2 = 0.f;
            for (int i = lane; i < NBLK; i += 32) t2 += __ldcg(&g_errpart[p][i]);
#pragma unroll
            for (int off = 16; off; off >>= 1)
                t2 += __shfl_xor_sync(0xffffffffu, t2, off);
            if (lane == 0) s_bcast = t2;
        }
        if (r == 0 && tid == 0) {
            *(volatile unsigned*)&g_du[p ^ 1][b] = 0u;
            *(volatile unsigned*)&g_dv[p ^ 1][b] = 0u;
        }
        float du_it = __uint_as_float(*(volatile unsigned*)&g_du[p][b]);
        __syncthreads();

        bool v_full    = !(colvalid && 2.f * (acc_du + du_it) <= WB);
        bool build_col = v_full && (2.f * du_it <= WB);

        if (v_full) {
            // ---- FULL v-pass: online scan over own chunk ----
            float m0 = -3.0e38f, s0 = 0.f, m1 = -3.0e38f, s1 = 0.f;
            for (int idx = 0; idx < cnt; idx++) {
                float2 c = cr2[(size_t)idx * 512 + tid];
                float u0 = s_u[idx];
                float x0 = u0 - c.x, x1 = u0 - c.y;
                bool g = (x0 >= m0 + K_CUT) || (x1 >= m1 + K_CUT);
                if (__any_sync(0xffffffffu, g)) {
                    float n0 = fmaxf(m0, x0), n1 = fmaxf(m1, x1);
                    s0 *= ex2f((m0 - n0) * K_L2E_EPS);
                    s1 *= ex2f((m1 - n1) * K_L2E_EPS);
                    float t;
                    t = x0 - n0; if (t >= K_CUT) s0 += ex2f(t * K_L2E_EPS);
                    t = x1 - n1; if (t >= K_CUT) s1 += ex2f(t * K_L2E_EPS);
                    m0 = n0; m1 = n1;
                }
            }
            ((float4*)g_part)[blockIdx.x * 512 + tid] = make_float4(m0, s0, m1, s1);
            if (build_col) {       // second scan vs local chunk max (superset)
                float th0 = m0 - W_WIN, th1 = m1 - W_WIN;
                int gc0 = (b << 10) + 2 * tid;
                int sg0 = gc0 * 18 + r, sg1 = (gc0 + 1) * 18 + r;
                int c0 = 0, c1 = 0;
                for (int idx = 0; idx < cnt; idx++) {
                    float2 c = cr2[(size_t)idx * 512 + tid];
                    float u0 = s_u[idx];
                    if (u0 - c.x >= th0) {
                        if (c0 < SEGCAP) g_clist[(size_t)sg0 * SEGCAP + c0] =
                            make_int2(row0 + idx, __float_as_int(c.x));
                        c0++;
                    }
                    if (u0 - c.y >= th1) {
                        if (c1 < SEGCAP) g_clist[(size_t)sg1 * SEGCAP + c1] =
                            make_int2(row0 + idx, __float_as_int(c.y));
                        c1++;
                    }
                }
                g_ccnt[sg0] = c0; g_ccnt[sg1] = c1;
            }
        } else {
            // ---- CHEAP v-pass (segment candidates, warp/owned column) ----
            float dvm = 0.f;
            for (int ci = warp; ci < cnt; ci += NWARP) {
                int gcol = (b << 10) + row0 + ci;
                int segb = gcol * 18;
                int myc = (lane < 18) ? g_ccnt[segb + lane] : 0;
                bool ovf = __any_sync(0xffffffffu, myc > SEGCAP);
                float m, s;
                if (!ovf) {
                    float lm = -3.0e38f, ls = 0.f;
                    for (int k = 0; k < myc; k++) {
                        int2 en = g_clist[(size_t)(segb + lane) * SEGCAP + k];
                        float x = __ldcg(&g_u[(b << 10) + en.x]) - __int_as_float(en.y);
                        VUPS(lm, ls, x);
                    }
                    m = lm; s = ls;
                } else {
                    float lm = -3.0e38f, ls = 0.f;
                    const float* cp = g_C + ((size_t)b << 20) + row0 + ci;
                    for (int i = lane; i < 1024; i += 32) {
                        float x = __ldcg(&g_u[(b << 10) + i]) - cp[(size_t)i << 10];
                        VUPS(lm, ls, x);
                    }
                    m = lm; s = ls;
                }
#pragma unroll
                for (int off = 16; off; off >>= 1) {
                    float om = __shfl_xor_sync(0xffffffffu, m, off);
                    float os = __shfl_xor_sync(0xffffffffu, s, off);
                    PCOMB(m, s, om, os);
                }
                if (lane == 0) {
                    float nv = K_EPSLOGMU - m - 1e-3f * __logf(s);
                    dvm = fmaxf(dvm, fabsf(nv - __ldcg(&g_v[gcol])));
                    g_v[gcol] = nv;
                }
            }
            if (lane == 0) s_redm[warp] = dvm;
            __syncthreads();
            if (warp == 0) {
                float t3 = (lane < NWARP) ? s_redm[lane] : 0.f;
#pragma unroll
                for (int off = 16; off; off >>= 1)
                    t3 = fmaxf(t3, __shfl_xor_sync(0xffffffffu, t3, off));
                if (lane == 0) atomicMax(&g_dv[p][b], __float_as_uint(t3));
            }
        }

        grid_barrier(++bar);                     // B: partials/lists/cheap-v done

        if (v_full) {
            // owner combine of own columns -> g_v, dv
            float dvm = 0.f;
            for (int jj = tid; jj < cnt; jj += NTHR) {
                int col = row0 + jj, gcol = (b << 10) + col;
                float M = -3.0e38f, S = 0.f;
#pragma unroll
                for (int rr = 0; rr < RPB; rr++) {
                    float2 q = __ldcg(&g_part[(b * RPB + rr) * 1024 + col]);
                    PCOMB(M, S, q.x, q.y);
                }
                float nv = K_EPSLOGMU - M - 1e-3f * __logf(S);
                dvm = fmaxf(dvm, fabsf(nv - __ldcg(&g_v[gcol])));
                g_v[gcol] = nv;
            }
#pragma unroll
            for (int off = 16; off; off >>= 1)
                dvm = fmaxf(dvm, __shfl_xor_sync(0xffffffffu, dvm, off));
            if (lane == 0) s_redm[warp] = dvm;
            __syncthreads();
            if (warp == 0) {
                float t3 = (lane < NWARP) ? s_redm[lane] : 0.f;
#pragma unroll
                for (int off = 16; off; off >>= 1)
                    t3 = fmaxf(t3, __shfl_xor_sync(0xffffffffu, t3, off));
                if (lane == 0) atomicMax(&g_dv[p][b], __float_as_uint(t3));
            }
        }

        grid_barrier(++bar);                     // C: g_v + dv final

        float dv_it = __uint_as_float(*(volatile unsigned*)&g_dv[p][b]);
        if (u_full && build_row) { rowvalid = true; acc_dv = dv_it; }
        else                     { acc_dv += dv_it; }
        if (v_full && build_col) { colvalid = true; acc_du = 0.f; }
        else                     { acc_du += du_it; }
        dv_last = dv_it;
        if (s_bcast * (1.0f / 16.0f) < 0.1f) break;
    }

    // ---- final transport cost ----
    for (int j = tid; j < 1024; j += NTHR)
        s_v[j] = __ldcg(&g_v[(b << 10) + j]);
    __syncthreads();

    float acc = 0.f;
    for (int idx = warp; idx < cnt; idx += NWARP) {
        float ui = s_u[idx];
        const float4* cr = (const float4*)(g_C + ((size_t)((b << 10) + row0 + idx) << 10));
#pragma unroll
        for (int k = 0; k < 8; k++) {
            float4 c = cr[k * 32 + lane];
            float4 v = sv4[k * 32 + lane];
            float t;
            t = ui + v.x - c.x; if (t > -0.04f) acc += ex2f(t * K_L2E_EPS) * c.x;
            t = ui + v.y - c.y; if (t > -0.04f) acc += ex2f(t * K_L2E_EPS) * c.y;
            t = ui + v.z - c.z; if (t > -0.04f) acc += ex2f(t * K_L2E_EPS) * c.z;
            t = ui + v.w - c.w; if (t > -0.04f) acc += ex2f(t * K_L2E_EPS) * c.w;
        }
    }
#pragma unroll
    for (int off = 16; off; off >>= 1)
        acc += __shfl_xor_sync(0xffffffffu, acc, off);
    if (lane == 0) s_red[warp] = acc;
    __syncthreads();
    if (warp == 0) {
        float t2 = (lane < NWARP) ? s_red[lane] : 0.f;
#pragma unroll
        for (int off = 16; off; off >>= 1)
            t2 += __shfl_xor_sync(0xffffffffu, t2, off);
        if (lane == 0) g_costpart[blockIdx.x] = t2;
    }
    grid_barrier(++bar);

    if (blockIdx.x == 0 && warp == 0) {
        float t2 = 0.f;
        for (int i = lane; i < NBLK; i += 32) t2 += __ldcg(&g_costpart[i]);
#pragma unroll
        for (int off = 16; off; off >>= 1)
            t2 += __shfl_xor_sync(0xffffffffu, t2, off);
        if (lane == 0) out[0] = t2 * (1.0f / 16.0f);
    }
}

// ---------------------------------------------------------------------------
extern "C" void kernel_launch(void* const* d_in, const int* in_sizes, int n_in,
                              void* d_out, int out_size) {
    const float* X = (const float*)d_in[0];
    const float* Y = (const float*)d_in[1];

    dim3 cgrid(32, 32, 16);
    compute_C_kernel<<<cgrid, 256>>>(X, Y);

    sinkhorn_kernel<<<NBLK, NTHR>>>((float*)d_out);
}

// round 15
// speedup vs baseline: 2.0109x; 2.0109x over previous
#include <cuda_runtime.h>

// ---------------------------------------------------------------------------
// Sinkhorn (Wasserstein) loss, B=16, N=M=1024, D=32, EPS=1e-3, THRESH=0.1
// Round 11: revert to R6 structure (best: 2813us) + f32x2 packed adds.
// g_C stores -C so every (v - C) / (u - C) is one add.rn.f32x2 per 2 elems
// (bitwise identical to scalar FADD => no numerical change).
// ---------------------------------------------------------------------------

#define BB    16
#define NN    1024
#define NBLK  288            // 18 row-chunk blocks per batch * 16 batches
#define RPB   18
#define NTHR  512
#define NWARP 16
#define CHUNK 57             // last block gets 1024-17*57=55

#define K_EPSLOGMU  (-6.9314616e-3f)   // EPS*log(1/1024+1e-8)
#define K_L2E_EPS   (1442.6950409f)    // log2(e)/EPS
#define K_CUT       (-0.032f)          // drop terms below 2^-46 of max

typedef unsigned long long u64;

__device__ float  g_C[16u * 1024u * 1024u];     // holds -C[b][i][j]
__device__ float2 g_part[2][NBLK * 1024];       // (m,s) per (block,col), parity
__device__ float  g_errpart[2][NBLK];
__device__ float  g_costpart[NBLK];
__device__ unsigned g_count;
__device__ unsigned g_release;

__device__ __forceinline__ float ex2f(float x) {
    float r;
    asm("ex2.approx.ftz.f32 %0, %1;" : "=f"(r) : "f"(x));
    return r;
}
__device__ __forceinline__ u64 addx2(u64 a, u64 b) {   // two IEEE fp32 adds
    u64 r;
    asm("add.rn.f32x2 %0, %1, %2;" : "=l"(r) : "l"(a), "l"(b));
    return r;
}
__device__ __forceinline__ void unpk(float& lo, float& hi, u64 p) {
    asm("mov.b64 {%0, %1}, %2;" : "=f"(lo), "=f"(hi) : "l"(p));
}
__device__ __forceinline__ u64 pk(float lo, float hi) {
    u64 r;
    asm("mov.b64 %0, {%1, %2};" : "=l"(r) : "f"(lo), "f"(hi));
    return r;
}

// ---------------------------------------------------------------------------
// Stores NEGATED cost: g_C = -(sum_d (x-y)^2). 32x32 tile per block.
__global__ void compute_C_kernel(const float* __restrict__ X,
                                 const float* __restrict__ Y) {
    __shared__ float xs[32][33];
    __shared__ float ys[32][33];
    int b  = blockIdx.z;
    int i0 = blockIdx.y * 32;
    int j0 = blockIdx.x * 32;
    int tid = threadIdx.x;

    if (blockIdx.x == 0 && blockIdx.y == 0 && blockIdx.z == 0 && tid == 0) {
        g_count = 0u; g_release = 0u;
    }

    const float* xp = X + ((size_t)(b * NN + i0)) * 32;
    const float* yp = Y + ((size_t)(b * NN + j0)) * 32;
    for (int idx = tid; idx < 1024; idx += 256) {
        xs[idx >> 5][idx & 31] = xp[idx];
        ys[idx >> 5][idx & 31] = yp[idx];
    }
    __syncthreads();

    int tx = tid & 31;
    int ty = tid >> 5;
    float a0 = 0.f, a1 = 0.f, a2 = 0.f, a3 = 0.f;
#pragma unroll
    for (int d = 0; d < 32; d++) {
        float yv = ys[tx][d];
        float d0 = xs[ty][d]      - yv; a0 += d0 * d0;
        float d1 = xs[ty +  8][d] - yv; a1 += d1 * d1;
        float d2 = xs[ty + 16][d] - yv; a2 += d2 * d2;
        float d3 = xs[ty + 24][d] - yv; a3 += d3 * d3;
    }
    size_t base = ((size_t)b << 20);
    g_C[base + ((size_t)(i0 + ty)      << 10) + j0 + tx] = -a0;
    g_C[base + ((size_t)(i0 + ty +  8) << 10) + j0 + tx] = -a1;
    g_C[base + ((size_t)(i0 + ty + 16) << 10) + j0 + tx] = -a2;
    g_C[base + ((size_t)(i0 + ty + 24) << 10) + j0 + tx] = -a3;
}

// ---------------------------------------------------------------------------
// Grid barrier. 288 blocks, 2 co-resident/SM guaranteed by launch_bounds(512,2).
__device__ __forceinline__ void grid_barrier(unsigned target) {
    __syncthreads();
    if (threadIdx.x == 0) {
        __threadfence();
        if (atomicAdd(&g_count, 1u) == NBLK - 1u) {
            g_count = 0u;
            __threadfence();
            atomicAdd(&g_release, 1u);
        } else {
            while (*((volatile unsigned*)&g_release) < target) { __nanosleep(32); }
        }
        __threadfence();
    }
    __syncthreads();
}

#define PCOMB(M, S, pm, ps) do {                                              \
    if ((pm) > (M)) {                                                         \
        float d_ = (M) - (pm);                                                \
        (S) = (S) * ((d_ >= K_CUT) ? ex2f(d_ * K_L2E_EPS) : 0.f) + (ps);      \
        (M) = (pm);                                                           \
    } else {                                                                  \
        float d_ = (pm) - (M);                                                \
        if (d_ >= K_CUT) (S) += (ps) * ex2f(d_ * K_L2E_EPS);                  \
    }                                                                         \
} while (0)

// ---------------------------------------------------------------------------
__global__ __launch_bounds__(NTHR, 2) void sinkhorn_kernel(float* __restrict__ out) {
    __shared__ __align__(16) float s_v[1024];
    __shared__ float s_u[64];
    __shared__ u64   s_up[64];            // (u,u) packed for the v-pass
    __shared__ float s_red[NWARP];
    __shared__ float s_bcast;

    int tid  = threadIdx.x;
    int lane = tid & 31;
    int warp = tid >> 5;
    int b    = blockIdx.x / RPB;
    int r    = blockIdx.x % RPB;
    int row0 = r * CHUNK;
    int cnt  = (r == RPB - 1) ? (NN - row0) : CHUNK;
    const ulonglong2* sv2 = (const ulonglong2*)s_v;
    unsigned bar = 0;
    int p = 0;

    if (tid < 64) { s_u[tid] = 0.f; s_up[tid] = 0ull; }

    for (int iter = 0; iter < 100; iter++) {
        p = iter & 1;
        // ---- combine v partials (written to buffer p^1 last iteration) ----
        if (iter == 0) {
            for (int j = tid; j < 1024; j += NTHR) s_v[j] = 0.f;
        } else {
            const float2* gp = g_part[p ^ 1];
            for (int j = tid; j < 1024; j += NTHR) {
                float M = -3.0e38f, S = 0.f;
#pragma unroll
                for (int rr = 0; rr < RPB; rr++) {
                    float2 q = __ldcg(&gp[(b * RPB + rr) * 1024 + j]);
                    PCOMB(M, S, q.x, q.y);
                }
                s_v[j] = K_EPSLOGMU - M - 1e-3f * __logf(S);
            }
        }
        __syncthreads();

        // ---- u pass: warp per row, logsumexp of (v_j + nC_ij) ----
        float e = 0.f;
        for (int idx = warp; idx < cnt; idx += NWARP) {
            const ulonglong2* cr =
                (const ulonglong2*)(g_C + ((size_t)b << 20) + ((size_t)(row0 + idx) << 10));
            float ma = -3.0e38f, mb = -3.0e38f;
#pragma unroll
            for (int k = 0; k < 8; k += 2) {
                ulonglong2 c0 = cr[k * 32 + lane];
                ulonglong2 c1 = cr[(k + 1) * 32 + lane];
                ulonglong2 v0 = sv2[k * 32 + lane];
                ulonglong2 v1 = sv2[(k + 1) * 32 + lane];
                u64 xa = addx2(v0.x, c0.x), xb = addx2(v0.y, c0.y);
                u64 xc = addx2(v1.x, c1.x), xd = addx2(v1.y, c1.y);
                float f0, f1, f2, f3, f4, f5, f6, f7;
                unpk(f0, f1, xa); unpk(f2, f3, xb);
                unpk(f4, f5, xc); unpk(f6, f7, xd);
                ma = fmaxf(ma, fmaxf(fmaxf(f0, f1), fmaxf(f2, f3)));
                mb = fmaxf(mb, fmaxf(fmaxf(f4, f5), fmaxf(f6, f7)));
            }
            float m = fmaxf(ma, mb);
#pragma unroll
            for (int off = 16; off; off >>= 1)
                m = fmaxf(m, __shfl_xor_sync(0xffffffffu, m, off));
            u64 mneg2 = pk(-m, -m);
            float s = 0.f;
#pragma unroll
            for (int k = 0; k < 8; k++) {           // rows hot in L1
                ulonglong2 c = cr[k * 32 + lane];
                ulonglong2 v = sv2[k * 32 + lane];
                u64 t01 = addx2(addx2(v.x, c.x), mneg2);
                u64 t23 = addx2(addx2(v.y, c.y), mneg2);
                float t0, t1, t2, t3;
                unpk(t0, t1, t01); unpk(t2, t3, t23);
                float mx = fmaxf(fmaxf(t0, t1), fmaxf(t2, t3));
                if (__any_sync(0xffffffffu, mx >= K_CUT)) {
                    if (t0 >= K_CUT) s += ex2f(t0 * K_L2E_EPS);
                    if (t1 >= K_CUT) s += ex2f(t1 * K_L2E_EPS);
                    if (t2 >= K_CUT) s += ex2f(t2 * K_L2E_EPS);
                    if (t3 >= K_CUT) s += ex2f(t3 * K_L2E_EPS);
                }
            }
#pragma unroll
            for (int off = 16; off; off >>= 1)
                s += __shfl_xor_sync(0xffffffffu, s, off);
            if (lane == 0) {
                float nv = K_EPSLOGMU - m - 1e-3f * __logf(s);
                e += fabsf(nv - s_u[idx]);
                s_u[idx] = nv;
                s_up[idx] = pk(nv, nv);
            }
        }
        if (lane == 0) s_red[warp] = e;
        __syncthreads();                    // s_u/s_up complete + s_red ready
        if (warp == 0) {
            float t2 = (lane < NWARP) ? s_red[lane] : 0.f;
#pragma unroll
            for (int off = 16; off; off >>= 1)
                t2 += __shfl_xor_sync(0xffffffffu, t2, off);
            if (lane == 0) g_errpart[p][blockIdx.x] = t2;
        }

        // ---- v pass: vote-gated chunked column logsumexp of (u_i + nC_ij).
        {
            float m0 = -3.0e38f, s0 = 0.f, m1 = -3.0e38f, s1 = 0.f;
            const u64* crp = (const u64*)(g_C + ((size_t)b << 20) + ((size_t)row0 << 10));
            int idx = 0;
            for (; idx + 4 <= cnt; idx += 4) {
                u64 xa = addx2(s_up[idx],     crp[(size_t)(idx + 0) * 512 + tid]);
                u64 xb = addx2(s_up[idx + 1], crp[(size_t)(idx + 1) * 512 + tid]);
                u64 xc = addx2(s_up[idx + 2], crp[(size_t)(idx + 2) * 512 + tid]);
                u64 xd = addx2(s_up[idx + 3], crp[(size_t)(idx + 3) * 512 + tid]);
                float x0a, x1a, x0b, x1b, x0c, x1c, x0d, x1d;
                unpk(x0a, x1a, xa); unpk(x0b, x1b, xb);
                unpk(x0c, x1c, xc); unpk(x0d, x1d, xd);
                float cm0 = fmaxf(fmaxf(x0a, x0b), fmaxf(x0c, x0d));
                float cm1 = fmaxf(fmaxf(x1a, x1b), fmaxf(x1c, x1d));
                bool g = (cm0 >= m0 + K_CUT) || (cm1 >= m1 + K_CUT);
                if (__any_sync(0xffffffffu, g)) {
                    float n0 = fmaxf(m0, cm0);
                    float n1 = fmaxf(m1, cm1);
                    s0 *= ex2f((m0 - n0) * K_L2E_EPS);   // exact 1.0 when unchanged
                    s1 *= ex2f((m1 - n1) * K_L2E_EPS);
                    float t;
                    t = x0a - n0; if (t >= K_CUT) s0 += ex2f(t * K_L2E_EPS);
                    t = x0b - n0; if (t >= K_CUT) s0 += ex2f(t * K_L2E_EPS);
                    t = x0c - n0; if (t >= K_CUT) s0 += ex2f(t * K_L2E_EPS);
                    t = x0d - n0; if (t >= K_CUT) s0 += ex2f(t * K_L2E_EPS);
                    t = x1a - n1; if (t >= K_CUT) s1 += ex2f(t * K_L2E_EPS);
                    t = x1b - n1; if (t >= K_CUT) s1 += ex2f(t * K_L2E_EPS);
                    t = x1c - n1; if (t >= K_CUT) s1 += ex2f(t * K_L2E_EPS);
                    t = x1d - n1; if (t >= K_CUT) s1 += ex2f(t * K_L2E_EPS);
                    m0 = n0; m1 = n1;
                }
            }
            for (; idx < cnt; idx++) {       // tail rows (1-3)
                u64 xa = addx2(s_up[idx], crp[(size_t)idx * 512 + tid]);
                float x0, x1;
                unpk(x0, x1, xa);
                bool g = (x0 >= m0 + K_CUT) || (x1 >= m1 + K_CUT);
                if (__any_sync(0xffffffffu, g)) {
                    float n0 = fmaxf(m0, x0);
                    float n1 = fmaxf(m1, x1);
                    s0 *= ex2f((m0 - n0) * K_L2E_EPS);
                    s1 *= ex2f((m1 - n1) * K_L2E_EPS);
                    float t;
                    t = x0 - n0; if (t >= K_CUT) s0 += ex2f(t * K_L2E_EPS);
                    t = x1 - n1; if (t >= K_CUT) s1 += ex2f(t * K_L2E_EPS);
                    m0 = n0; m1 = n1;
                }
            }
            ((float4*)g_part[p])[blockIdx.x * 512 + tid] = make_float4(m0, s0, m1, s1);
        }

        grid_barrier(++bar);   // ONE barrier: err parts + v partials all visible

        // total err (deterministic fixed-order sum; identical in every block)
        if (warp == 0) {
            float t2 = 0.f;
            for (int i = lane; i < NBLK; i += 32) t2 += __ldcg(&g_errpart[p][i]);
#pragma unroll
            for (int off = 16; off; off >>= 1)
                t2 += __shfl_xor_sync(0xffffffffu, t2, off);
            if (lane == 0) s_bcast = t2;
        }
        __syncthreads();
        if (s_bcast * (1.0f / 16.0f) < 0.1f) break;
    }

    // ---- final v combine (from buffer p) + transport cost ----
    {
        const float2* gp = g_part[p];
        for (int j = tid; j < 1024; j += NTHR) {
            float M = -3.0e38f, S = 0.f;
#pragma unroll
            for (int rr = 0; rr < RPB; rr++) {
                float2 q = __ldcg(&gp[(b * RPB + rr) * 1024 + j]);
                PCOMB(M, S, q.x, q.y);
            }
            s_v[j] = K_EPSLOGMU - M - 1e-3f * __logf(S);
        }
    }
    __syncthreads();

    const float* Cb = g_C + ((size_t)b << 20);     // negated C
    const float4* sv4 = (const float4*)s_v;
    float acc = 0.f;
    for (int idx = warp; idx < cnt; idx += NWARP) {
        float ui = s_u[idx];
        const float4* cr = (const float4*)(Cb + ((size_t)(row0 + idx) << 10));
#pragma unroll
        for (int k = 0; k < 8; k++) {
            float4 c = cr[k * 32 + lane];          // c = -C
            float4 v = sv4[k * 32 + lane];
            float t;
            t = ui + v.x + c.x; if (t > -0.04f) acc -= ex2f(t * K_L2E_EPS) * c.x;
            t = ui + v.y + c.y; if (t > -0.04f) acc -= ex2f(t * K_L2E_EPS) * c.y;
            t = ui + v.z + c.z; if (t > -0.04f) acc -= ex2f(t * K_L2E_EPS) * c.z;
            t = ui + v.w + c.w; if (t > -0.04f) acc -= ex2f(t * K_L2E_EPS) * c.w;
        }
    }
#pragma unroll
    for (int off = 16; off; off >>= 1)
        acc += __shfl_xor_sync(0xffffffffu, acc, off);
    if (lane == 0) s_red[warp] = acc;
    __syncthreads();
    if (warp == 0) {
        float t2 = (lane < NWARP) ? s_red[lane] : 0.f;
#pragma unroll
        for (int off = 16; off; off >>= 1)
            t2 += __shfl_xor_sync(0xffffffffu, t2, off);
        if (lane == 0) g_costpart[blockIdx.x] = t2;
    }
    grid_barrier(++bar);

    if (blockIdx.x == 0 && warp == 0) {
        float t2 = 0.f;
        for (int i = lane; i < NBLK; i += 32) t2 += __ldcg(&g_costpart[i]);
#pragma unroll
        for (int off = 16; off; off >>= 1)
            t2 += __shfl_xor_sync(0xffffffffu, t2, off);
        if (lane == 0) out[0] = t2 * (1.0f / 16.0f);
    }
}

// ---------------------------------------------------------------------------
extern "C" void kernel_launch(void* const* d_in, const int* in_sizes, int n_in,
                              void* d_out, int out_size) {
    const float* X = (const float*)d_in[0];   // output [16,1024,32]
    const float* Y = (const float*)d_in[1];   // labels [16,1024,32]

    dim3 cgrid(32, 32, 16);
    compute_C_kernel<<<cgrid, 256>>>(X, Y);

    sinkhorn_kernel<<<NBLK, NTHR>>>((float*)d_out);
}

// round 16
// speedup vs baseline: 2.3500x; 1.1687x over previous
#include <cuda_runtime.h>

// ---------------------------------------------------------------------------
// Sinkhorn (Wasserstein) loss, B=16, N=M=1024, D=32, EPS=1e-3, THRESH=0.1
// Round 15: R11 base (f32x2 packed adds, negated C) + OWNER-COMBINE:
// each block combines only its own 57 columns (warp-per-col, parallel lane
// loads + 5-step shuffle-PCOMB tree) and publishes v via g_v; second grid
// barrier shares it. Removes the 18x-redundant all-column combine and the
// parity double-buffers (barrier intervals fence all cross-block buffers).
// ---------------------------------------------------------------------------

#define BB    16
#define NN    1024
#define NBLK  288            // 18 row-chunk blocks per batch * 16 batches
#define RPB   18
#define NTHR  512
#define NWARP 16
#define CHUNK 57             // last block gets 1024-17*57=55

#define K_EPSLOGMU  (-6.9314616e-3f)   // EPS*log(1/1024+1e-8)
#define K_L2E_EPS   (1442.6950409f)    // log2(e)/EPS
#define K_CUT       (-0.032f)          // drop terms below 2^-46 of max

typedef unsigned long long u64;

__device__ float  g_C[16u * 1024u * 1024u];     // holds -C[b][i][j]
__device__ float2 g_part[NBLK * 1024];          // (m,s) per (block,col)
__device__ float  g_v[16384];                   // combined v per (b,col)
__device__ float  g_errpart[NBLK];
__device__ float  g_costpart[NBLK];
__device__ unsigned g_count;
__device__ unsigned g_release;

__device__ __forceinline__ float ex2f(float x) {
    float r;
    asm("ex2.approx.ftz.f32 %0, %1;" : "=f"(r) : "f"(x));
    return r;
}
__device__ __forceinline__ u64 addx2(u64 a, u64 b) {   // two IEEE fp32 adds
    u64 r;
    asm("add.rn.f32x2 %0, %1, %2;" : "=l"(r) : "l"(a), "l"(b));
    return r;
}
__device__ __forceinline__ void unpk(float& lo, float& hi, u64 p) {
    asm("mov.b64 {%0, %1}, %2;" : "=f"(lo), "=f"(hi) : "l"(p));
}
__device__ __forceinline__ u64 pk(float lo, float hi) {
    u64 r;
    asm("mov.b64 %0, {%1, %2};" : "=l"(r) : "f"(lo), "f"(hi));
    return r;
}

// ---------------------------------------------------------------------------
// Stores NEGATED cost: g_C = -(sum_d (x-y)^2). 32x32 tile per block.
__global__ void compute_C_kernel(const float* __restrict__ X,
                                 const float* __restrict__ Y) {
    __shared__ float xs[32][33];
    __shared__ float ys[32][33];
    int b  = blockIdx.z;
    int i0 = blockIdx.y * 32;
    int j0 = blockIdx.x * 32;
    int tid = threadIdx.x;

    if (blockIdx.x == 0 && blockIdx.y == 0 && blockIdx.z == 0 && tid == 0) {
        g_count = 0u; g_release = 0u;
    }

    const float* xp = X + ((size_t)(b * NN + i0)) * 32;
    const float* yp = Y + ((size_t)(b * NN + j0)) * 32;
    for (int idx = tid; idx < 1024; idx += 256) {
        xs[idx >> 5][idx & 31] = xp[idx];
        ys[idx >> 5][idx & 31] = yp[idx];
    }
    __syncthreads();

    int tx = tid & 31;
    int ty = tid >> 5;
    float a0 = 0.f, a1 = 0.f, a2 = 0.f, a3 = 0.f;
#pragma unroll
    for (int d = 0; d < 32; d++) {
        float yv = ys[tx][d];
        float d0 = xs[ty][d]      - yv; a0 += d0 * d0;
        float d1 = xs[ty +  8][d] - yv; a1 += d1 * d1;
        float d2 = xs[ty + 16][d] - yv; a2 += d2 * d2;
        float d3 = xs[ty + 24][d] - yv; a3 += d3 * d3;
    }
    size_t base = ((size_t)b << 20);
    g_C[base + ((size_t)(i0 + ty)      << 10) + j0 + tx] = -a0;
    g_C[base + ((size_t)(i0 + ty +  8) << 10) + j0 + tx] = -a1;
    g_C[base + ((size_t)(i0 + ty + 16) << 10) + j0 + tx] = -a2;
    g_C[base + ((size_t)(i0 + ty + 24) << 10) + j0 + tx] = -a3;
}

// ---------------------------------------------------------------------------
// Grid barrier. 288 blocks, 2 co-resident/SM guaranteed by launch_bounds(512,2).
__device__ __forceinline__ void grid_barrier(unsigned target) {
    __syncthreads();
    if (threadIdx.x == 0) {
        __threadfence();
        if (atomicAdd(&g_count, 1u) == NBLK - 1u) {
            g_count = 0u;
            __threadfence();
            atomicAdd(&g_release, 1u);
        } else {
            while (*((volatile unsigned*)&g_release) < target) { __nanosleep(32); }
        }
        __threadfence();
    }
    __syncthreads();
}

#define PCOMB(M, S, pm, ps) do {                                              \
    if ((pm) > (M)) {                                                         \
        float d_ = (M) - (pm);                                                \
        (S) = (S) * ((d_ >= K_CUT) ? ex2f(d_ * K_L2E_EPS) : 0.f) + (ps);      \
        (M) = (pm);                                                           \
    } else {                                                                  \
        float d_ = (pm) - (M);                                                \
        if (d_ >= K_CUT) (S) += (ps) * ex2f(d_ * K_L2E_EPS);                  \
    }                                                                         \
} while (0)

// ---------------------------------------------------------------------------
__global__ __launch_bounds__(NTHR, 2) void sinkhorn_kernel(float* __restrict__ out) {
    __shared__ __align__(16) float s_v[1024];
    __shared__ float s_u[64];
    __shared__ u64   s_up[64];            // (u,u) packed for the v-pass
    __shared__ float s_red[NWARP];
    __shared__ float s_bcast;

    int tid  = threadIdx.x;
    int lane = tid & 31;
    int warp = tid >> 5;
    int b    = blockIdx.x / RPB;
    int r    = blockIdx.x % RPB;
    int row0 = r * CHUNK;
    int cnt  = (r == RPB - 1) ? (NN - row0) : CHUNK;
    const ulonglong2* sv2 = (const ulonglong2*)s_v;
    unsigned bar = 0;

    if (tid < 64) { s_u[tid] = 0.f; s_up[tid] = 0ull; }

    for (int iter = 0; iter < 100; iter++) {
        // ---- fetch combined v (owner-published last iteration) ----
        if (iter == 0) {
            for (int j = tid; j < 1024; j += NTHR) s_v[j] = 0.f;
        } else {
            for (int j = tid; j < 1024; j += NTHR)
                s_v[j] = __ldcg(&g_v[(b << 10) + j]);
        }
        __syncthreads();

        // ---- u pass: warp per row, logsumexp of (v_j + nC_ij) ----
        float e = 0.f;
        for (int idx = warp; idx < cnt; idx += NWARP) {
            const ulonglong2* cr =
                (const ulonglong2*)(g_C + ((size_t)b << 20) + ((size_t)(row0 + idx) << 10));
            float ma = -3.0e38f, mb = -3.0e38f;
#pragma unroll
            for (int k = 0; k < 8; k += 2) {
                ulonglong2 c0 = cr[k * 32 + lane];
                ulonglong2 c1 = cr[(k + 1) * 32 + lane];
                ulonglong2 v0 = sv2[k * 32 + lane];
                ulonglong2 v1 = sv2[(k + 1) * 32 + lane];
                u64 xa = addx2(v0.x, c0.x), xb = addx2(v0.y, c0.y);
                u64 xc = addx2(v1.x, c1.x), xd = addx2(v1.y, c1.y);
                float f0, f1, f2, f3, f4, f5, f6, f7;
                unpk(f0, f1, xa); unpk(f2, f3, xb);
                unpk(f4, f5, xc); unpk(f6, f7, xd);
                ma = fmaxf(ma, fmaxf(fmaxf(f0, f1), fmaxf(f2, f3)));
                mb = fmaxf(mb, fmaxf(fmaxf(f4, f5), fmaxf(f6, f7)));
            }
            float m = fmaxf(ma, mb);
#pragma unroll
            for (int off = 16; off; off >>= 1)
                m = fmaxf(m, __shfl_xor_sync(0xffffffffu, m, off));
            u64 mneg2 = pk(-m, -m);
            float s = 0.f;
#pragma unroll
            for (int k = 0; k < 8; k++) {           // rows hot in L1
                ulonglong2 c = cr[k * 32 + lane];
                ulonglong2 v = sv2[k * 32 + lane];
                u64 t01 = addx2(addx2(v.x, c.x), mneg2);
                u64 t23 = addx2(addx2(v.y, c.y), mneg2);
                float t0, t1, t2, t3;
                unpk(t0, t1, t01); unpk(t2, t3, t23);
                float mx = fmaxf(fmaxf(t0, t1), fmaxf(t2, t3));
                if (__any_sync(0xffffffffu, mx >= K_CUT)) {
                    if (t0 >= K_CUT) s += ex2f(t0 * K_L2E_EPS);
                    if (t1 >= K_CUT) s += ex2f(t1 * K_L2E_EPS);
                    if (t2 >= K_CUT) s += ex2f(t2 * K_L2E_EPS);
                    if (t3 >= K_CUT) s += ex2f(t3 * K_L2E_EPS);
                }
            }
#pragma unroll
            for (int off = 16; off; off >>= 1)
                s += __shfl_xor_sync(0xffffffffu, s, off);
            if (lane == 0) {
                float nv = K_EPSLOGMU - m - 1e-3f * __logf(s);
                e += fabsf(nv - s_u[idx]);
                s_u[idx] = nv;
                s_up[idx] = pk(nv, nv);
            }
        }
        if (lane == 0) s_red[warp] = e;
        __syncthreads();                    // s_u/s_up complete + s_red ready
        if (warp == 0) {
            float t2 = (lane < NWARP) ? s_red[lane] : 0.f;
#pragma unroll
            for (int off = 16; off; off >>= 1)
                t2 += __shfl_xor_sync(0xffffffffu, t2, off);
            if (lane == 0) g_errpart[blockIdx.x] = t2;
        }

        // ---- v pass: vote-gated chunked column logsumexp of (u_i + nC_ij) ----
        {
            float m0 = -3.0e38f, s0 = 0.f, m1 = -3.0e38f, s1 = 0.f;
            const u64* crp = (const u64*)(g_C + ((size_t)b << 20) + ((size_t)row0 << 10));
            int idx = 0;
            for (; idx + 4 <= cnt; idx += 4) {
                u64 xa = addx2(s_up[idx],     crp[(size_t)(idx + 0) * 512 + tid]);
                u64 xb = addx2(s_up[idx + 1], crp[(size_t)(idx + 1) * 512 + tid]);
                u64 xc = addx2(s_up[idx + 2], crp[(size_t)(idx + 2) * 512 + tid]);
                u64 xd = addx2(s_up[idx + 3], crp[(size_t)(idx + 3) * 512 + tid]);
                float x0a, x1a, x0b, x1b, x0c, x1c, x0d, x1d;
                unpk(x0a, x1a, xa); unpk(x0b, x1b, xb);
                unpk(x0c, x1c, xc); unpk(x0d, x1d, xd);
                float cm0 = fmaxf(fmaxf(x0a, x0b), fmaxf(x0c, x0d));
                float cm1 = fmaxf(fmaxf(x1a, x1b), fmaxf(x1c, x1d));
                bool g = (cm0 >= m0 + K_CUT) || (cm1 >= m1 + K_CUT);
                if (__any_sync(0xffffffffu, g)) {
                    float n0 = fmaxf(m0, cm0);
                    float n1 = fmaxf(m1, cm1);
                    s0 *= ex2f((m0 - n0) * K_L2E_EPS);   // exact 1.0 when unchanged
                    s1 *= ex2f((m1 - n1) * K_L2E_EPS);
                    float t;
                    t = x0a - n0; if (t >= K_CUT) s0 += ex2f(t * K_L2E_EPS);
                    t = x0b - n0; if (t >= K_CUT) s0 += ex2f(t * K_L2E_EPS);
                    t = x0c - n0; if (t >= K_CUT) s0 += ex2f(t * K_L2E_EPS);
                    t = x0d - n0; if (t >= K_CUT) s0 += ex2f(t * K_L2E_EPS);
                    t = x1a - n1; if (t >= K_CUT) s1 += ex2f(t * K_L2E_EPS);
                    t = x1b - n1; if (t >= K_CUT) s1 += ex2f(t * K_L2E_EPS);
                    t = x1c - n1; if (t >= K_CUT) s1 += ex2f(t * K_L2E_EPS);
                    t = x1d - n1; if (t >= K_CUT) s1 += ex2f(t * K_L2E_EPS);
                    m0 = n0; m1 = n1;
                }
            }
            for (; idx < cnt; idx++) {       // tail rows (1-3)
                u64 xa = addx2(s_up[idx], crp[(size_t)idx * 512 + tid]);
                float x0, x1;
                unpk(x0, x1, xa);
                bool g = (x0 >= m0 + K_CUT) || (x1 >= m1 + K_CUT);
                if (__any_sync(0xffffffffu, g)) {
                    float n0 = fmaxf(m0, x0);
                    float n1 = fmaxf(m1, x1);
                    s0 *= ex2f((m0 - n0) * K_L2E_EPS);
                    s1 *= ex2f((m1 - n1) * K_L2E_EPS);
                    float t;
                    t = x0 - n0; if (t >= K_CUT) s0 += ex2f(t * K_L2E_EPS);
                    t = x1 - n1; if (t >= K_CUT) s1 += ex2f(t * K_L2E_EPS);
                    m0 = n0; m1 = n1;
                }
            }
            ((float4*)g_part)[blockIdx.x * 512 + tid] = make_float4(m0, s0, m1, s1);
        }

        grid_barrier(++bar);       // ---- A: partials + err parts final ----

        // total err (between A and B: no writer can touch g_errpart here)
        if (warp == 0) {
            float t2 = 0.f;
            for (int i = lane; i < NBLK; i += 32) t2 += __ldcg(&g_errpart[i]);
#pragma unroll
            for (int off = 16; off; off >>= 1)
                t2 += __shfl_xor_sync(0xffffffffu, t2, off);
            if (lane == 0) s_bcast = t2;
        }

        // owner-combine own columns -> g_v (warp per column, tree merge)
        for (int ci = warp; ci < cnt; ci += NWARP) {
            int col = row0 + ci;
            float M = -3.0e38f, S = 0.f;
            if (lane < RPB) {
                float2 q = __ldcg(&g_part[(b * RPB + lane) * 1024 + col]);
                M = q.x; S = q.y;
            }
#pragma unroll
            for (int off = 16; off; off >>= 1) {
                float om = __shfl_xor_sync(0xffffffffu, M, off);
                float os = __shfl_xor_sync(0xffffffffu, S, off);
                PCOMB(M, S, om, os);
            }
            if (lane == 0)
                g_v[(b << 10) + col] = K_EPSLOGMU - M - 1e-3f * __logf(S);
        }

        grid_barrier(++bar);       // ---- B: g_v final, s_bcast published ----

        if (s_bcast * (1.0f / 16.0f) < 0.1f) break;
    }

    // ---- final transport cost (current v from g_v) ----
    for (int j = tid; j < 1024; j += NTHR)
        s_v[j] = __ldcg(&g_v[(b << 10) + j]);
    __syncthreads();

    const float* Cb = g_C + ((size_t)b << 20);     // negated C
    const float4* sv4 = (const float4*)s_v;
    float acc = 0.f;
    for (int idx = warp; idx < cnt; idx += NWARP) {
        float ui = s_u[idx];
        const float4* cr = (const float4*)(Cb + ((size_t)(row0 + idx) << 10));
#pragma unroll
        for (int k = 0; k < 8; k++) {
            float4 c = cr[k * 32 + lane];          // c = -C
            float4 v = sv4[k * 32 + lane];
            float t;
            t = ui + v.x + c.x; if (t > -0.04f) acc -= ex2f(t * K_L2E_EPS) * c.x;
            t = ui + v.y + c.y; if (t > -0.04f) acc -= ex2f(t * K_L2E_EPS) * c.y;
            t = ui + v.z + c.z; if (t > -0.04f) acc -= ex2f(t * K_L2E_EPS) * c.z;
            t = ui + v.w + c.w; if (t > -0.04f) acc -= ex2f(t * K_L2E_EPS) * c.w;
        }
    }
#pragma unroll
    for (int off = 16; off; off >>= 1)
        acc += __shfl_xor_sync(0xffffffffu, acc, off);
    if (lane == 0) s_red[warp] = acc;
    __syncthreads();
    if (warp == 0) {
        float t2 = (lane < NWARP) ? s_red[lane] : 0.f;
#pragma unroll
        for (int off = 16; off; off >>= 1)
            t2 += __shfl_xor_sync(0xffffffffu, t2, off);
        if (lane == 0) g_costpart[blockIdx.x] = t2;
    }
    grid_barrier(++bar);

    if (blockIdx.x == 0 && warp == 0) {
        float t2 = 0.f;
        for (int i = lane; i < NBLK; i += 32) t2 += __ldcg(&g_costpart[i]);
#pragma unroll
        for (int off = 16; off; off >>= 1)
            t2 += __shfl_xor_sync(0xffffffffu, t2, off);
        if (lane == 0) out[0] = t2 * (1.0f / 16.0f);
    }
}

// ---------------------------------------------------------------------------
extern "C" void kernel_launch(void* const* d_in, const int* in_sizes, int n_in,
                              void* d_out, int out_size) {
    const float* X = (const float*)d_in[0];   // output [16,1024,32]
    const float* Y = (const float*)d_in[1];   // labels [16,1024,32]

    dim3 cgrid(32, 32, 16);
    compute_C_kernel<<<cgrid, 256>>>(X, Y);

    sinkhorn_kernel<<<NBLK, NTHR>>>((float*)d_out);
}